// round 11
// baseline (speedup 1.0000x reference)
#include <cuda_runtime.h>
#include <math.h>

#define NN 50000
#define EE 800000
#define GG 64
#define HC 256
#define C2 32

// ---------------- static scratch (allocation-free rule; zero-initialized) --
__device__ float  d_XL1[(size_t)NN * HC];
__device__ float  d_XR1[(size_t)NN * HC];
__device__ float  d_H1 [(size_t)NN * HC];
__device__ float  d_XL2[(size_t)NN * C2];
__device__ float  d_XR2[(size_t)NN * C2];
__device__ int    d_deg[NN];        // zeroed by k_scan after use
__device__ int    d_cur[NN];        // zeroed by k_gat1 after use
__device__ int    d_row[NN + 1];
__device__ int2   d_eidx[EE];       // {src, bitcast(ew)}
__device__ float  d_gsum[GG * C2];  // zeroed by k_head after use
__device__ float  d_gcnt[GG];       // zeroed by k_head after use
__device__ int    d_is64;

__device__ __forceinline__ int ld_idx(const void* p, size_t i) {
    return d_is64 ? (int)((const long long*)p)[i] : ((const int*)p)[i];
}

// ---------------- helpers ----------------
__device__ __forceinline__ void load8(float* d, const float* p) {
    float4 a = *(const float4*)p;
    float4 b = *(const float4*)(p + 4);
    d[0]=a.x; d[1]=a.y; d[2]=a.z; d[3]=a.w;
    d[4]=b.x; d[5]=b.y; d[6]=b.z; d[7]=b.w;
}
__device__ __forceinline__ void store8(float* p, const float* d) {
    *(float4*)p       = make_float4(d[0],d[1],d[2],d[3]);
    *(float4*)(p + 4) = make_float4(d[4],d[5],d[6],d[7]);
}

__device__ __forceinline__ unsigned f2tf32(float f) {
    unsigned r;
    asm("cvt.rna.tf32.f32 %0, %1;" : "=r"(r) : "f"(f));
    return r;
}

__device__ __forceinline__ void mma_tf32(float* c, const unsigned* a, const unsigned* b) {
    asm("mma.sync.aligned.m16n8k8.row.col.f32.tf32.tf32.f32 "
        "{%0,%1,%2,%3}, {%4,%5,%6,%7}, {%8,%9}, {%0,%1,%2,%3};"
        : "+f"(c[0]), "+f"(c[1]), "+f"(c[2]), "+f"(c[3])
        : "r"(a[0]), "r"(a[1]), "r"(a[2]), "r"(a[3]), "r"(b[0]), "r"(b[1]));
}

// ---------------- dtype detect (1 warp) ----------------
__global__ void k_detect(const void* ei) {
    int t = threadIdx.x;
    const long long* p = (const long long*)ei;
    bool ok = true;
    #pragma unroll
    for (int q = 0; q < 2; q++) {
        long long a = p[t + 32 * q];
        long long b = p[(size_t)EE + t + 32 * q];
        ok &= (a >= 0 && a < NN && b >= 0 && b < NN);
    }
    unsigned m = __ballot_sync(0xffffffffu, ok);
    if (t == 0) d_is64 = (m == 0xffffffffu) ? 1 : 0;
}

// ---------------- CSR build ----------------
__global__ void k_hist(const void* __restrict__ ei) {
    int e = blockIdx.x * blockDim.x + threadIdx.x;
    if (e < EE) atomicAdd(&d_deg[ld_idx(ei, (size_t)EE + e)], 1);
}

__global__ void k_scan() {
    __shared__ int sm[1024];
    int t = threadIdx.x;
    const int chunk = (NN + 1023) >> 10;             // 49
    int s0 = t * chunk;
    int s1 = s0 + chunk; if (s1 > NN) s1 = NN;
    int local = 0;
    for (int i = s0; i < s1; i++) local += d_deg[i];
    sm[t] = local;
    __syncthreads();
    for (int off = 1; off < 1024; off <<= 1) {
        int v = (t >= off) ? sm[t - off] : 0;
        __syncthreads();
        sm[t] += v;
        __syncthreads();
    }
    int run = (t > 0) ? sm[t - 1] : 0;
    for (int i = s0; i < s1; i++) {
        d_row[i] = run;
        run += d_deg[i];
        d_deg[i] = 0;                               // self-clean for next replay
    }
    if (t == 1023) d_row[NN] = sm[1023];
}

__global__ void k_scatter(const void* __restrict__ ei,
                          const float* __restrict__ ew) {
    int e = blockIdx.x * blockDim.x + threadIdx.x;
    if (e < EE) {
        int dst = ld_idx(ei, (size_t)EE + e);
        int pos = atomicAdd(&d_cur[dst], 1);
        d_eidx[d_row[dst] + pos] = make_int2(ld_idx(ei, e), __float_as_int(ew[e]));
    }
}

// ---------------- GEMM1 via tf32 tensor cores (smem pre-converted) -------
__global__ void __launch_bounds__(256, 2)
k_gemm1_tc(const float* __restrict__ X,
           const float* __restrict__ WL, const float* __restrict__ bL,
           const float* __restrict__ WR, const float* __restrict__ bR,
           float* __restrict__ outL, float* __restrict__ outR) {
    const int mat = blockIdx.y >> 1;
    const int nt  = blockIdx.y & 1;
    const float* W    = mat ? WR : WL;
    const float* bias = mat ? bR : bL;
    float* out        = mat ? outR : outL;

    __shared__ unsigned As[128][36];
    __shared__ unsigned Ws[32][132];

    const int t = threadIdx.x;
    const int warp = t >> 5, lane = t & 31;
    const int g = lane >> 2, tig = lane & 3;
    const int m0 = blockIdx.x << 7;
    const int n0 = nt << 7;
    const int wm = (warp >> 2) << 6;
    const int wn = (warp & 3) << 5;

    float acc[4][4][4];
    #pragma unroll
    for (int a = 0; a < 4; a++)
        #pragma unroll
        for (int b = 0; b < 4; b++)
            #pragma unroll
            for (int c = 0; c < 4; c++) acc[a][b][c] = 0.f;

    #pragma unroll 1
    for (int kc = 0; kc < 4; kc++) {
        const int k0 = kc << 5;
        #pragma unroll
        for (int q = t; q < 1024; q += 256) {
            int r  = q >> 3;
            int c4 = (q & 7) << 2;
            int row = m0 + r;
            float4 v = (row < NN) ? *(const float4*)(X + (size_t)row * 128 + k0 + c4)
                                  : make_float4(0.f, 0.f, 0.f, 0.f);
            As[r][c4+0] = f2tf32(v.x); As[r][c4+1] = f2tf32(v.y);
            As[r][c4+2] = f2tf32(v.z); As[r][c4+3] = f2tf32(v.w);
        }
        #pragma unroll
        for (int q = t; q < 1024; q += 256) {
            int kk = q >> 5;
            int c4 = (q & 31) << 2;
            float4 v = *(const float4*)(W + (size_t)(k0 + kk) * 256 + n0 + c4);
            Ws[kk][c4+0] = f2tf32(v.x); Ws[kk][c4+1] = f2tf32(v.y);
            Ws[kk][c4+2] = f2tf32(v.z); Ws[kk][c4+3] = f2tf32(v.w);
        }
        __syncthreads();
        #pragma unroll
        for (int ks = 0; ks < 4; ks++) {
            const int kk = ks << 3;
            unsigned a[4][4], b[4][2];
            #pragma unroll
            for (int mi = 0; mi < 4; mi++) {
                int rb = wm + (mi << 4);
                a[mi][0] = As[rb + g    ][kk + tig    ];
                a[mi][1] = As[rb + g + 8][kk + tig    ];
                a[mi][2] = As[rb + g    ][kk + tig + 4];
                a[mi][3] = As[rb + g + 8][kk + tig + 4];
            }
            #pragma unroll
            for (int ni = 0; ni < 4; ni++) {
                int col = wn + (ni << 3) + g;
                b[ni][0] = Ws[kk + tig    ][col];
                b[ni][1] = Ws[kk + tig + 4][col];
            }
            #pragma unroll
            for (int mi = 0; mi < 4; mi++)
                #pragma unroll
                for (int ni = 0; ni < 4; ni++)
                    mma_tf32(acc[mi][ni], a[mi], b[ni]);
        }
        __syncthreads();
    }
    #pragma unroll
    for (int ni = 0; ni < 4; ni++) {
        int col = n0 + wn + (ni << 3) + (tig << 1);
        float b0 = bias[col], b1 = bias[col + 1];
        #pragma unroll
        for (int mi = 0; mi < 4; mi++) {
            int r0 = m0 + wm + (mi << 4) + g;
            if (r0 < NN)
                *(float2*)(out + (size_t)r0 * 256 + col)
                    = make_float2(acc[mi][ni][0] + b0, acc[mi][ni][1] + b1);
            if (r0 + 8 < NN)
                *(float2*)(out + (size_t)(r0 + 8) * 256 + col)
                    = make_float2(acc[mi][ni][2] + b0, acc[mi][ni][3] + b1);
        }
    }
}

// ---------------- GEMM2 via tf32 tensor cores (smem pre-converted) -------
__global__ void __launch_bounds__(256, 2)
k_gemm2_tc(const float* __restrict__ X,
           const float* __restrict__ WL, const float* __restrict__ bL,
           const float* __restrict__ WR, const float* __restrict__ bR,
           float* __restrict__ outL, float* __restrict__ outR) {
    const float* W    = blockIdx.y ? WR : WL;
    const float* bias = blockIdx.y ? bR : bL;
    float* out        = blockIdx.y ? outR : outL;

    __shared__ unsigned As[128][36];
    __shared__ unsigned Ws[32][36];

    const int t = threadIdx.x;
    const int warp = t >> 5, lane = t & 31;
    const int g = lane >> 2, tig = lane & 3;
    const int m0 = blockIdx.x << 7;
    const int wm = warp << 4;

    float acc[4][4];
    #pragma unroll
    for (int a = 0; a < 4; a++)
        #pragma unroll
        for (int c = 0; c < 4; c++) acc[a][c] = 0.f;

    #pragma unroll 1
    for (int kc = 0; kc < 8; kc++) {
        const int k0 = kc << 5;
        #pragma unroll
        for (int q = t; q < 1024; q += 256) {
            int r  = q >> 3;
            int c4 = (q & 7) << 2;
            int row = m0 + r;
            float4 v = (row < NN) ? *(const float4*)(X + (size_t)row * 256 + k0 + c4)
                                  : make_float4(0.f, 0.f, 0.f, 0.f);
            As[r][c4+0] = f2tf32(v.x); As[r][c4+1] = f2tf32(v.y);
            As[r][c4+2] = f2tf32(v.z); As[r][c4+3] = f2tf32(v.w);
        }
        if (t < 256) {
            int kk = t >> 3;
            int c4 = (t & 7) << 2;
            float4 v = *(const float4*)(W + (size_t)(k0 + kk) * 32 + c4);
            Ws[kk][c4+0] = f2tf32(v.x); Ws[kk][c4+1] = f2tf32(v.y);
            Ws[kk][c4+2] = f2tf32(v.z); Ws[kk][c4+3] = f2tf32(v.w);
        }
        __syncthreads();
        #pragma unroll
        for (int ks = 0; ks < 4; ks++) {
            const int kk = ks << 3;
            unsigned a[4], b[4][2];
            a[0] = As[wm + g    ][kk + tig    ];
            a[1] = As[wm + g + 8][kk + tig    ];
            a[2] = As[wm + g    ][kk + tig + 4];
            a[3] = As[wm + g + 8][kk + tig + 4];
            #pragma unroll
            for (int ni = 0; ni < 4; ni++) {
                int col = (ni << 3) + g;
                b[ni][0] = Ws[kk + tig    ][col];
                b[ni][1] = Ws[kk + tig + 4][col];
            }
            #pragma unroll
            for (int ni = 0; ni < 4; ni++)
                mma_tf32(acc[ni], a, b[ni]);
        }
        __syncthreads();
    }
    #pragma unroll
    for (int ni = 0; ni < 4; ni++) {
        int col = (ni << 3) + (tig << 1);
        float b0 = bias[col], b1 = bias[col + 1];
        int r0 = m0 + wm + g;
        if (r0 < NN)
            *(float2*)(out + (size_t)r0 * 32 + col)
                = make_float2(acc[ni][0] + b0, acc[ni][1] + b1);
        if (r0 + 8 < NN)
            *(float2*)(out + (size_t)(r0 + 8) * 32 + col)
                = make_float2(acc[ni][2] + b0, acc[ni][3] + b1);
    }
}

// ---------------- GAT layer 1: warp/node, unroll-2, depth-2 prefetch -----
__device__ __forceinline__ float gat1_edge(const float* xl, const float* xr,
                                           const float* we, const float* at,
                                           float ew) {
    float s = 0.f;
    #pragma unroll
    for (int i = 0; i < 8; i++) {
        float v = xl[i] + xr[i] + ew * we[i];
        v = fmaxf(v, 0.2f * v);                     // leaky_relu 0.2
        s = fmaf(v, at[i], s);
    }
    s += __shfl_xor_sync(0xffffffffu, s, 1);
    s += __shfl_xor_sync(0xffffffffu, s, 2);
    s = fminf(fmaxf(s, -60.f), 60.f);
    return __expf(s);
}

__global__ void k_gat1(const float* __restrict__ We, const float* __restrict__ att,
                       const float* __restrict__ bias) {
    int n    = (blockIdx.x * blockDim.x + threadIdx.x) >> 5;
    int lane = threadIdx.x & 31;
    if (n >= NN) return;
    int base = lane << 3;
    float we[8], at[8], xr[8];
    load8(we, We + base);
    load8(at, att + base);
    load8(xr, d_XR1 + (size_t)n * 256 + base);
    int rs = d_row[n], re = d_row[n + 1];
    int deg = re - rs;
    if (lane == 0) d_cur[n] = 0;                    // self-clean for next replay
    float denom = 0.f;
    float acc[8];
    #pragma unroll
    for (int i = 0; i < 8; i++) acc[i] = 0.f;
    if (deg > 0) {
        const int2* ep = d_eidx + rs;
        const int last = deg - 1;
        int2 e0 = ep[0];
        int2 e1 = ep[min(1, last)];
        float ew0 = __int_as_float(e0.y), ew1 = __int_as_float(e1.y);
        float xl0[8], xl1[8];
        load8(xl0, d_XL1 + (size_t)e0.x * 256 + base);
        load8(xl1, d_XL1 + (size_t)e1.x * 256 + base);
        #pragma unroll 1
        for (int j = 0; j < deg; j += 2) {
            int2 e2 = ep[min(j + 2, last)];
            int2 e3 = ep[min(j + 3, last)];
            float xl2[8], xl3[8];
            load8(xl2, d_XL1 + (size_t)e2.x * 256 + base);
            load8(xl3, d_XL1 + (size_t)e3.x * 256 + base);
            float p0 = gat1_edge(xl0, xr, we, at, ew0);
            denom += p0;
            #pragma unroll
            for (int i = 0; i < 8; i++) acc[i] = fmaf(p0, xl0[i], acc[i]);
            if (j + 1 < deg) {
                float p1 = gat1_edge(xl1, xr, we, at, ew1);
                denom += p1;
                #pragma unroll
                for (int i = 0; i < 8; i++) acc[i] = fmaf(p1, xl1[i], acc[i]);
            }
            #pragma unroll
            for (int i = 0; i < 8; i++) { xl0[i] = xl2[i]; xl1[i] = xl3[i]; }
            ew0 = __int_as_float(e2.y); ew1 = __int_as_float(e3.y);
        }
    }
    float inv = (deg > 0) ? 1.f / denom : 0.f;
    float bi[8], o[8];
    load8(bi, bias + base);
    #pragma unroll
    for (int i = 0; i < 8; i++) {
        float v = fmaf(acc[i], inv, bi[i]);
        o[i] = (v > 0.f) ? v : (__expf(v) - 1.f);   // elu fused
    }
    store8(d_H1 + (size_t)n * 256 + base, o);
}

// ---------------- GAT layer 2 (H=1,C=32) + pooling, unroll-2 -------------
__device__ __forceinline__ float gat2_edge(float xl, float xr, float we,
                                           float at, float ew) {
    float v = xl + xr + ew * we;
    v = fmaxf(v, 0.2f * v);
    float s = v * at;
    #pragma unroll
    for (int o = 16; o > 0; o >>= 1) s += __shfl_xor_sync(0xffffffffu, s, o);
    s = fminf(fmaxf(s, -60.f), 60.f);
    return __expf(s);
}

__global__ void k_gat2(const float* __restrict__ We, const float* __restrict__ att,
                       const float* __restrict__ bias,
                       const void* __restrict__ batch) {
    int n    = (blockIdx.x * blockDim.x + threadIdx.x) >> 5;
    int lane = threadIdx.x & 31;
    if (n >= NN) return;
    float we = We[lane], at = att[lane];
    float xr = d_XR2[(size_t)n * 32 + lane];
    int rs = d_row[n], re = d_row[n + 1];
    int deg = re - rs;
    float denom = 0.f, acc = 0.f;
    if (deg > 0) {
        const int2* ep = d_eidx + rs;
        const int last = deg - 1;
        int2 e0 = ep[0];
        int2 e1 = ep[min(1, last)];
        float ew0 = __int_as_float(e0.y), ew1 = __int_as_float(e1.y);
        float xl0 = d_XL2[(size_t)e0.x * 32 + lane];
        float xl1 = d_XL2[(size_t)e1.x * 32 + lane];
        #pragma unroll 1
        for (int j = 0; j < deg; j += 2) {
            int2 e2 = ep[min(j + 2, last)];
            int2 e3 = ep[min(j + 3, last)];
            float xl2 = d_XL2[(size_t)e2.x * 32 + lane];
            float xl3 = d_XL2[(size_t)e3.x * 32 + lane];
            float p0 = gat2_edge(xl0, xr, we, at, ew0);
            denom += p0;
            acc = fmaf(p0, xl0, acc);
            if (j + 1 < deg) {
                float p1 = gat2_edge(xl1, xr, we, at, ew1);
                denom += p1;
                acc = fmaf(p1, xl1, acc);
            }
            xl0 = xl2; xl1 = xl3;
            ew0 = __int_as_float(e2.y); ew1 = __int_as_float(e3.y);
        }
    }
    float val = ((deg > 0) ? acc / denom : 0.f) + bias[lane];
    int g = ld_idx(batch, n);
    atomicAdd(&d_gsum[g * 32 + lane], val);
    if (lane == 0) atomicAdd(&d_gcnt[g], 1.f);
}

// ---------------- head (+ self-clean of gsum/gcnt) ----------------------
__global__ void k_head(const float* __restrict__ Wlin, const float* __restrict__ blin,
                       float* __restrict__ out) {
    __shared__ float logits[GG * 10];
    __shared__ float mrow[GG], lse[GG];
    int t = threadIdx.x;                            // 640 threads
    if (t < GG * 10) {
        int g = t / 10, o = t % 10;
        float cnt = fmaxf(d_gcnt[g], 1.f);
        float inv = 1.f / cnt;
        float acc = blin[o];
        #pragma unroll
        for (int c = 0; c < 32; c++)
            acc = fmaf(d_gsum[g * 32 + c] * inv, Wlin[c * 10 + o], acc);
        logits[t] = acc;
    }
    __syncthreads();
    // self-clean pooling buffers for the next replay
    for (int i = t; i < GG * C2; i += 640) d_gsum[i] = 0.f;
    if (t < GG) d_gcnt[t] = 0.f;
    if (t < GG) {
        float mx = -1e30f;
        #pragma unroll
        for (int o = 0; o < 10; o++) mx = fmaxf(mx, logits[t * 10 + o]);
        float s = 0.f;
        #pragma unroll
        for (int o = 0; o < 10; o++) s += expf(logits[t * 10 + o] - mx);
        mrow[t] = mx; lse[t] = logf(s);
    }
    __syncthreads();
    if (t < GG * 10) {
        int g = t / 10;
        out[t] = logits[t] - mrow[g] - lse[g];
    }
}

// ---------------- launch ----------------
extern "C" void kernel_launch(void* const* d_in, const int* in_sizes, int n_in,
                              void* d_out, int out_size) {
    const float* x     = (const float*)d_in[0];
    const float* ew    = (const float*)d_in[1];
    const float* Wl1   = (const float*)d_in[2];
    const float* bl1   = (const float*)d_in[3];
    const float* Wr1   = (const float*)d_in[4];
    const float* br1   = (const float*)d_in[5];
    const float* We1   = (const float*)d_in[6];
    const float* att1  = (const float*)d_in[7];
    const float* bias1 = (const float*)d_in[8];
    const float* Wl2   = (const float*)d_in[9];
    const float* bl2   = (const float*)d_in[10];
    const float* Wr2   = (const float*)d_in[11];
    const float* br2   = (const float*)d_in[12];
    const float* We2   = (const float*)d_in[13];
    const float* att2  = (const float*)d_in[14];
    const float* bias2 = (const float*)d_in[15];
    const float* Wlin  = (const float*)d_in[16];
    const float* blin  = (const float*)d_in[17];
    const void*  ei    = d_in[18];
    const void*  batch = d_in[19];
    float* out = (float*)d_out;

    void *pXL1, *pXR1, *pH1, *pXL2, *pXR2;
    cudaGetSymbolAddress(&pXL1, d_XL1);
    cudaGetSymbolAddress(&pXR1, d_XR1);
    cudaGetSymbolAddress(&pH1,  d_H1);
    cudaGetSymbolAddress(&pXL2, d_XL2);
    cudaGetSymbolAddress(&pXR2, d_XR2);

    k_detect<<<1, 32>>>(ei);
    k_hist<<<(EE + 255) / 256, 256>>>(ei);
    k_scan<<<1, 1024>>>();
    k_scatter<<<(EE + 255) / 256, 256>>>(ei, ew);

    k_gemm1_tc<<<dim3((NN + 127) / 128, 4), 256>>>(x, Wl1, bl1, Wr1, br1,
                                                   (float*)pXL1, (float*)pXR1);
    k_gat1<<<(NN * 32) / 256, 256>>>(We1, att1, bias1);
    k_gemm2_tc<<<dim3((NN + 127) / 128, 2), 256>>>((const float*)pH1, Wl2, bl2, Wr2, br2,
                                                   (float*)pXL2, (float*)pXR2);
    k_gat2<<<(NN * 32) / 256, 256>>>(We2, att2, bias2, batch);
    k_head<<<1, 640>>>(Wlin, blin, out);
}

// round 12
// speedup vs baseline: 1.1544x; 1.1544x over previous
#include <cuda_runtime.h>
#include <math.h>

#define NN 50000
#define EE 800000
#define GG 64
#define HC 256
#define C2 32

// ---------------- static scratch (allocation-free rule) ----------------
__device__ float  d_XL1[(size_t)NN * HC];
__device__ float  d_XR1[(size_t)NN * HC];
__device__ float  d_H1 [(size_t)NN * HC];
__device__ float  d_XL2[(size_t)NN * C2];
__device__ float  d_XR2[(size_t)NN * C2];
__device__ int    d_deg[NN];
__device__ int    d_cur[NN];
__device__ int    d_row[NN + 1];
__device__ int2   d_eidx[EE];                  // {src, bitcast(ew)}
__device__ float  d_gsum[GG * C2];
__device__ float  d_gcnt[GG];
__device__ int    d_is64;

__device__ __forceinline__ int ld_idx(const void* p, size_t i) {
    return d_is64 ? (int)((const long long*)p)[i] : ((const int*)p)[i];
}

// ---------------- helpers ----------------
__device__ __forceinline__ void load8(float* d, const float* p) {
    float4 a = *(const float4*)p;
    float4 b = *(const float4*)(p + 4);
    d[0]=a.x; d[1]=a.y; d[2]=a.z; d[3]=a.w;
    d[4]=b.x; d[5]=b.y; d[6]=b.z; d[7]=b.w;
}
__device__ __forceinline__ void store8(float* p, const float* d) {
    *(float4*)p       = make_float4(d[0],d[1],d[2],d[3]);
    *(float4*)(p + 4) = make_float4(d[4],d[5],d[6],d[7]);
}

__device__ __forceinline__ unsigned f2tf32(float f) {
    unsigned r;
    asm("cvt.rna.tf32.f32 %0, %1;" : "=r"(r) : "f"(f));
    return r;
}

__device__ __forceinline__ void mma_tf32(float* c, const unsigned* a, const unsigned* b) {
    asm("mma.sync.aligned.m16n8k8.row.col.f32.tf32.tf32.f32 "
        "{%0,%1,%2,%3}, {%4,%5,%6,%7}, {%8,%9}, {%0,%1,%2,%3};"
        : "+f"(c[0]), "+f"(c[1]), "+f"(c[2]), "+f"(c[3])
        : "r"(a[0]), "r"(a[1]), "r"(a[2]), "r"(a[3]), "r"(b[0]), "r"(b[1]));
}

// ---------------- init: zero scratch + index-dtype detect ----------------
__global__ void k_init(const void* ei) {
    int i = blockIdx.x * blockDim.x + threadIdx.x;
    if (i < NN) { d_deg[i] = 0; d_cur[i] = 0; }
    if (i < GG * C2) d_gsum[i] = 0.f;
    if (i < GG) d_gcnt[i] = 0.f;
    if (blockIdx.x == 0 && threadIdx.x < 32) {
        int t = threadIdx.x;
        const long long* p = (const long long*)ei;
        bool ok = true;
        #pragma unroll
        for (int q = 0; q < 2; q++) {
            long long a = p[t + 32 * q];
            long long b = p[(size_t)EE + t + 32 * q];
            ok &= (a >= 0 && a < NN && b >= 0 && b < NN);
        }
        unsigned m = __ballot_sync(0xffffffffu, ok);
        if (t == 0) d_is64 = (m == 0xffffffffu) ? 1 : 0;
    }
}

// ---------------- CSR build ----------------
__global__ void k_hist(const void* __restrict__ ei) {
    int e = blockIdx.x * blockDim.x + threadIdx.x;
    if (e < EE) atomicAdd(&d_deg[ld_idx(ei, (size_t)EE + e)], 1);
}

__global__ void k_scan() {
    __shared__ int sm[1024];
    int t = threadIdx.x;
    const int chunk = (NN + 1023) >> 10;             // 49
    int s0 = t * chunk;
    int s1 = s0 + chunk; if (s1 > NN) s1 = NN;
    int local = 0;
    for (int i = s0; i < s1; i++) local += d_deg[i];
    sm[t] = local;
    __syncthreads();
    for (int off = 1; off < 1024; off <<= 1) {
        int v = (t >= off) ? sm[t - off] : 0;
        __syncthreads();
        sm[t] += v;
        __syncthreads();
    }
    int run = (t > 0) ? sm[t - 1] : 0;
    for (int i = s0; i < s1; i++) { d_row[i] = run; run += d_deg[i]; }
    if (t == 1023) d_row[NN] = sm[1023];
}

__global__ void k_scatter(const void* __restrict__ ei,
                          const float* __restrict__ ew) {
    int e = blockIdx.x * blockDim.x + threadIdx.x;
    if (e < EE) {
        int dst = ld_idx(ei, (size_t)EE + e);
        int pos = atomicAdd(&d_cur[dst], 1);
        d_eidx[d_row[dst] + pos] = make_int2(ld_idx(ei, e), __float_as_int(ew[e]));
    }
}

// ---------------- GEMM1 via tf32 tensor cores ---------------------------
__global__ void __launch_bounds__(256, 2)
k_gemm1_tc(const float* __restrict__ X,
           const float* __restrict__ WL, const float* __restrict__ bL,
           const float* __restrict__ WR, const float* __restrict__ bR,
           float* __restrict__ outL, float* __restrict__ outR) {
    const int mat = blockIdx.y >> 1;
    const int nt  = blockIdx.y & 1;
    const float* W    = mat ? WR : WL;
    const float* bias = mat ? bR : bL;
    float* out        = mat ? outR : outL;

    __shared__ float As[128][36];
    __shared__ float Ws[32][132];

    const int t = threadIdx.x;
    const int warp = t >> 5, lane = t & 31;
    const int g = lane >> 2, tig = lane & 3;
    const int m0 = blockIdx.x << 7;
    const int n0 = nt << 7;
    const int wm = (warp >> 2) << 6;
    const int wn = (warp & 3) << 5;

    float acc[4][4][4];
    #pragma unroll
    for (int a = 0; a < 4; a++)
        #pragma unroll
        for (int b = 0; b < 4; b++)
            #pragma unroll
            for (int c = 0; c < 4; c++) acc[a][b][c] = 0.f;

    #pragma unroll 1
    for (int kc = 0; kc < 4; kc++) {
        const int k0 = kc << 5;
        #pragma unroll
        for (int q = t; q < 1024; q += 256) {
            int r  = q >> 3;
            int c4 = (q & 7) << 2;
            int row = m0 + r;
            float4 v = (row < NN) ? *(const float4*)(X + (size_t)row * 128 + k0 + c4)
                                  : make_float4(0.f, 0.f, 0.f, 0.f);
            As[r][c4+0] = v.x; As[r][c4+1] = v.y; As[r][c4+2] = v.z; As[r][c4+3] = v.w;
        }
        #pragma unroll
        for (int q = t; q < 1024; q += 256) {
            int kk = q >> 5;
            int c4 = (q & 31) << 2;
            float4 v = *(const float4*)(W + (size_t)(k0 + kk) * 256 + n0 + c4);
            Ws[kk][c4+0] = v.x; Ws[kk][c4+1] = v.y; Ws[kk][c4+2] = v.z; Ws[kk][c4+3] = v.w;
        }
        __syncthreads();
        #pragma unroll
        for (int ks = 0; ks < 4; ks++) {
            const int kk = ks << 3;
            unsigned a[4][4], b[4][2];
            #pragma unroll
            for (int mi = 0; mi < 4; mi++) {
                int rb = wm + (mi << 4);
                a[mi][0] = f2tf32(As[rb + g    ][kk + tig    ]);
                a[mi][1] = f2tf32(As[rb + g + 8][kk + tig    ]);
                a[mi][2] = f2tf32(As[rb + g    ][kk + tig + 4]);
                a[mi][3] = f2tf32(As[rb + g + 8][kk + tig + 4]);
            }
            #pragma unroll
            for (int ni = 0; ni < 4; ni++) {
                int col = wn + (ni << 3) + g;
                b[ni][0] = f2tf32(Ws[kk + tig    ][col]);
                b[ni][1] = f2tf32(Ws[kk + tig + 4][col]);
            }
            #pragma unroll
            for (int mi = 0; mi < 4; mi++)
                #pragma unroll
                for (int ni = 0; ni < 4; ni++)
                    mma_tf32(acc[mi][ni], a[mi], b[ni]);
        }
        __syncthreads();
    }
    #pragma unroll
    for (int ni = 0; ni < 4; ni++) {
        int col = n0 + wn + (ni << 3) + (tig << 1);
        float b0 = bias[col], b1 = bias[col + 1];
        #pragma unroll
        for (int mi = 0; mi < 4; mi++) {
            int r0 = m0 + wm + (mi << 4) + g;
            if (r0 < NN)
                *(float2*)(out + (size_t)r0 * 256 + col)
                    = make_float2(acc[mi][ni][0] + b0, acc[mi][ni][1] + b1);
            if (r0 + 8 < NN)
                *(float2*)(out + (size_t)(r0 + 8) * 256 + col)
                    = make_float2(acc[mi][ni][2] + b0, acc[mi][ni][3] + b1);
        }
    }
}

// ---------------- GEMM2 via tf32 tensor cores ---------------------------
__global__ void __launch_bounds__(256, 2)
k_gemm2_tc(const float* __restrict__ X,
           const float* __restrict__ WL, const float* __restrict__ bL,
           const float* __restrict__ WR, const float* __restrict__ bR,
           float* __restrict__ outL, float* __restrict__ outR) {
    const float* W    = blockIdx.y ? WR : WL;
    const float* bias = blockIdx.y ? bR : bL;
    float* out        = blockIdx.y ? outR : outL;

    __shared__ float As[128][36];
    __shared__ float Ws[32][36];

    const int t = threadIdx.x;
    const int warp = t >> 5, lane = t & 31;
    const int g = lane >> 2, tig = lane & 3;
    const int m0 = blockIdx.x << 7;
    const int wm = warp << 4;

    float acc[4][4];
    #pragma unroll
    for (int a = 0; a < 4; a++)
        #pragma unroll
        for (int c = 0; c < 4; c++) acc[a][c] = 0.f;

    #pragma unroll 1
    for (int kc = 0; kc < 8; kc++) {
        const int k0 = kc << 5;
        #pragma unroll
        for (int q = t; q < 1024; q += 256) {
            int r  = q >> 3;
            int c4 = (q & 7) << 2;
            int row = m0 + r;
            float4 v = (row < NN) ? *(const float4*)(X + (size_t)row * 256 + k0 + c4)
                                  : make_float4(0.f, 0.f, 0.f, 0.f);
            As[r][c4+0] = v.x; As[r][c4+1] = v.y; As[r][c4+2] = v.z; As[r][c4+3] = v.w;
        }
        if (t < 256) {
            int kk = t >> 3;
            int c4 = (t & 7) << 2;
            float4 v = *(const float4*)(W + (size_t)(k0 + kk) * 32 + c4);
            Ws[kk][c4+0] = v.x; Ws[kk][c4+1] = v.y; Ws[kk][c4+2] = v.z; Ws[kk][c4+3] = v.w;
        }
        __syncthreads();
        #pragma unroll
        for (int ks = 0; ks < 4; ks++) {
            const int kk = ks << 3;
            unsigned a[4], b[4][2];
            a[0] = f2tf32(As[wm + g    ][kk + tig    ]);
            a[1] = f2tf32(As[wm + g + 8][kk + tig    ]);
            a[2] = f2tf32(As[wm + g    ][kk + tig + 4]);
            a[3] = f2tf32(As[wm + g + 8][kk + tig + 4]);
            #pragma unroll
            for (int ni = 0; ni < 4; ni++) {
                int col = (ni << 3) + g;
                b[ni][0] = f2tf32(Ws[kk + tig    ][col]);
                b[ni][1] = f2tf32(Ws[kk + tig + 4][col]);
            }
            #pragma unroll
            for (int ni = 0; ni < 4; ni++)
                mma_tf32(acc[ni], a, b[ni]);
        }
        __syncthreads();
    }
    #pragma unroll
    for (int ni = 0; ni < 4; ni++) {
        int col = (ni << 3) + (tig << 1);
        float b0 = bias[col], b1 = bias[col + 1];
        int r0 = m0 + wm + g;
        if (r0 < NN)
            *(float2*)(out + (size_t)r0 * 32 + col)
                = make_float2(acc[ni][0] + b0, acc[ni][1] + b1);
        if (r0 + 8 < NN)
            *(float2*)(out + (size_t)(r0 + 8) * 32 + col)
                = make_float2(acc[ni][2] + b0, acc[ni][3] + b1);
    }
}

// ---------------- GAT layer 1: warp/node, unroll-2, depth-2 prefetch -----
__device__ __forceinline__ float gat1_edge(const float* xl, const float* xr,
                                           const float* we, const float* at,
                                           float ew) {
    float s = 0.f;
    #pragma unroll
    for (int i = 0; i < 8; i++) {
        float v = xl[i] + xr[i] + ew * we[i];
        v = (v > 0.f) ? v : 0.2f * v;               // leaky_relu 0.2
        s = fmaf(v, at[i], s);
    }
    s += __shfl_xor_sync(0xffffffffu, s, 1);
    s += __shfl_xor_sync(0xffffffffu, s, 2);
    s = fminf(fmaxf(s, -60.f), 60.f);
    return __expf(s);
}

__global__ void k_gat1(const float* __restrict__ We, const float* __restrict__ att,
                       const float* __restrict__ bias) {
    int n    = (blockIdx.x * blockDim.x + threadIdx.x) >> 5;
    int lane = threadIdx.x & 31;
    if (n >= NN) return;
    int base = lane << 3;
    float we[8], at[8], xr[8];
    load8(we, We + base);
    load8(at, att + base);
    load8(xr, d_XR1 + (size_t)n * 256 + base);
    int rs = d_row[n], re = d_row[n + 1];
    int deg = re - rs;
    float denom = 0.f;
    float acc[8];
    #pragma unroll
    for (int i = 0; i < 8; i++) acc[i] = 0.f;
    if (deg > 0) {
        const int2* ep = d_eidx + rs;
        const int last = deg - 1;
        int2 e0 = ep[0];
        int2 e1 = ep[min(1, last)];
        float ew0 = __int_as_float(e0.y), ew1 = __int_as_float(e1.y);
        float xl0[8], xl1[8];
        load8(xl0, d_XL1 + (size_t)e0.x * 256 + base);
        load8(xl1, d_XL1 + (size_t)e1.x * 256 + base);
        #pragma unroll 1
        for (int j = 0; j < deg; j += 2) {
            int2 e2 = ep[min(j + 2, last)];
            int2 e3 = ep[min(j + 3, last)];
            float xl2[8], xl3[8];
            load8(xl2, d_XL1 + (size_t)e2.x * 256 + base);
            load8(xl3, d_XL1 + (size_t)e3.x * 256 + base);
            float p0 = gat1_edge(xl0, xr, we, at, ew0);
            denom += p0;
            #pragma unroll
            for (int i = 0; i < 8; i++) acc[i] = fmaf(p0, xl0[i], acc[i]);
            if (j + 1 < deg) {
                float p1 = gat1_edge(xl1, xr, we, at, ew1);
                denom += p1;
                #pragma unroll
                for (int i = 0; i < 8; i++) acc[i] = fmaf(p1, xl1[i], acc[i]);
            }
            #pragma unroll
            for (int i = 0; i < 8; i++) { xl0[i] = xl2[i]; xl1[i] = xl3[i]; }
            ew0 = __int_as_float(e2.y); ew1 = __int_as_float(e3.y);
        }
    }
    float inv = (deg > 0) ? 1.f / denom : 0.f;
    float bi[8], o[8];
    load8(bi, bias + base);
    #pragma unroll
    for (int i = 0; i < 8; i++) {
        float v = fmaf(acc[i], inv, bi[i]);
        o[i] = (v > 0.f) ? v : (__expf(v) - 1.f);   // elu fused
    }
    store8(d_H1 + (size_t)n * 256 + base, o);
}

// ---------------- GAT layer 2 (H=1,C=32) + pooling, unroll-2 -------------
__device__ __forceinline__ float gat2_edge(float xl, float xr, float we,
                                           float at, float ew) {
    float v = xl + xr + ew * we;
    v = (v > 0.f) ? v : 0.2f * v;
    float s = v * at;
    #pragma unroll
    for (int o = 16; o > 0; o >>= 1) s += __shfl_xor_sync(0xffffffffu, s, o);
    s = fminf(fmaxf(s, -60.f), 60.f);
    return __expf(s);
}

__global__ void k_gat2(const float* __restrict__ We, const float* __restrict__ att,
                       const float* __restrict__ bias,
                       const void* __restrict__ batch) {
    int n    = (blockIdx.x * blockDim.x + threadIdx.x) >> 5;
    int lane = threadIdx.x & 31;
    if (n >= NN) return;
    float we = We[lane], at = att[lane];
    float xr = d_XR2[(size_t)n * 32 + lane];
    int rs = d_row[n], re = d_row[n + 1];
    int deg = re - rs;
    float denom = 0.f, acc = 0.f;
    if (deg > 0) {
        const int2* ep = d_eidx + rs;
        const int last = deg - 1;
        int2 e0 = ep[0];
        int2 e1 = ep[min(1, last)];
        float ew0 = __int_as_float(e0.y), ew1 = __int_as_float(e1.y);
        float xl0 = d_XL2[(size_t)e0.x * 32 + lane];
        float xl1 = d_XL2[(size_t)e1.x * 32 + lane];
        #pragma unroll 1
        for (int j = 0; j < deg; j += 2) {
            int2 e2 = ep[min(j + 2, last)];
            int2 e3 = ep[min(j + 3, last)];
            float xl2 = d_XL2[(size_t)e2.x * 32 + lane];
            float xl3 = d_XL2[(size_t)e3.x * 32 + lane];
            float p0 = gat2_edge(xl0, xr, we, at, ew0);
            denom += p0;
            acc = fmaf(p0, xl0, acc);
            if (j + 1 < deg) {
                float p1 = gat2_edge(xl1, xr, we, at, ew1);
                denom += p1;
                acc = fmaf(p1, xl1, acc);
            }
            xl0 = xl2; xl1 = xl3;
            ew0 = __int_as_float(e2.y); ew1 = __int_as_float(e3.y);
        }
    }
    float val = ((deg > 0) ? acc / denom : 0.f) + bias[lane];
    int g = ld_idx(batch, n);
    atomicAdd(&d_gsum[g * 32 + lane], val);
    if (lane == 0) atomicAdd(&d_gcnt[g], 1.f);
}

// ---------------- head ----------------
__global__ void k_head(const float* __restrict__ Wlin, const float* __restrict__ blin,
                       float* __restrict__ out) {
    __shared__ float logits[GG * 10];
    __shared__ float mrow[GG], lse[GG];
    int t = threadIdx.x;                            // 640 threads
    if (t < GG * 10) {
        int g = t / 10, o = t % 10;
        float cnt = fmaxf(d_gcnt[g], 1.f);
        float inv = 1.f / cnt;
        float acc = blin[o];
        #pragma unroll
        for (int c = 0; c < 32; c++)
            acc = fmaf(d_gsum[g * 32 + c] * inv, Wlin[c * 10 + o], acc);
        logits[t] = acc;
    }
    __syncthreads();
    if (t < GG) {
        float mx = -1e30f;
        #pragma unroll
        for (int o = 0; o < 10; o++) mx = fmaxf(mx, logits[t * 10 + o]);
        float s = 0.f;
        #pragma unroll
        for (int o = 0; o < 10; o++) s += expf(logits[t * 10 + o] - mx);
        mrow[t] = mx; lse[t] = logf(s);
    }
    __syncthreads();
    if (t < GG * 10) {
        int g = t / 10;
        out[t] = logits[t] - mrow[g] - lse[g];
    }
}

// ---------------- launch ----------------
extern "C" void kernel_launch(void* const* d_in, const int* in_sizes, int n_in,
                              void* d_out, int out_size) {
    const float* x     = (const float*)d_in[0];
    const float* ew    = (const float*)d_in[1];
    const float* Wl1   = (const float*)d_in[2];
    const float* bl1   = (const float*)d_in[3];
    const float* Wr1   = (const float*)d_in[4];
    const float* br1   = (const float*)d_in[5];
    const float* We1   = (const float*)d_in[6];
    const float* att1  = (const float*)d_in[7];
    const float* bias1 = (const float*)d_in[8];
    const float* Wl2   = (const float*)d_in[9];
    const float* bl2   = (const float*)d_in[10];
    const float* Wr2   = (const float*)d_in[11];
    const float* br2   = (const float*)d_in[12];
    const float* We2   = (const float*)d_in[13];
    const float* att2  = (const float*)d_in[14];
    const float* bias2 = (const float*)d_in[15];
    const float* Wlin  = (const float*)d_in[16];
    const float* blin  = (const float*)d_in[17];
    const void*  ei    = d_in[18];
    const void*  batch = d_in[19];
    float* out = (float*)d_out;

    void *pXL1, *pXR1, *pH1, *pXL2, *pXR2;
    cudaGetSymbolAddress(&pXL1, d_XL1);
    cudaGetSymbolAddress(&pXR1, d_XR1);
    cudaGetSymbolAddress(&pH1,  d_H1);
    cudaGetSymbolAddress(&pXL2, d_XL2);
    cudaGetSymbolAddress(&pXR2, d_XR2);

    // one-time host objects for the capture fork (no device memory involved)
    static cudaStream_t s2 = nullptr;
    static cudaEvent_t  evFork = nullptr, evJoin = nullptr;
    if (s2 == nullptr) {
        cudaStreamCreateWithFlags(&s2, cudaStreamNonBlocking);
        cudaEventCreateWithFlags(&evFork, cudaEventDisableTiming);
        cudaEventCreateWithFlags(&evJoin, cudaEventDisableTiming);
    }

    // fork: gemm1 (needs only x/W) runs concurrently with the CSR build
    cudaEventRecord(evFork, 0);
    cudaStreamWaitEvent(s2, evFork, 0);
    k_gemm1_tc<<<dim3((NN + 127) / 128, 4), 256, 0, s2>>>(
        x, Wl1, bl1, Wr1, br1, (float*)pXL1, (float*)pXR1);
    cudaEventRecord(evJoin, s2);

    // CSR chain on the main (captured) stream
    k_init<<<(NN + 255) / 256, 256>>>(ei);
    k_hist<<<(EE + 255) / 256, 256>>>(ei);
    k_scan<<<1, 1024>>>();
    k_scatter<<<(EE + 255) / 256, 256>>>(ei, ew);

    // join: gat1 needs both gemm1 outputs and the CSR
    cudaStreamWaitEvent(0, evJoin, 0);
    k_gat1<<<(NN * 32) / 256, 256>>>(We1, att1, bias1);
    k_gemm2_tc<<<dim3((NN + 127) / 128, 2), 256>>>((const float*)pH1, Wl2, bl2, Wr2, br2,
                                                   (float*)pXL2, (float*)pXR2);
    k_gat2<<<(NN * 32) / 256, 256>>>(We2, att2, bias2, batch);
    k_head<<<1, 640>>>(Wlin, blin, out);
}

// round 14
// speedup vs baseline: 1.3087x; 1.1337x over previous
#include <cuda_runtime.h>
#include <math.h>

#define NN 50000
#define EE 800000
#define GG 64
#define HC 256
#define C2 32
#define NBLK 49   // ceil(NN / 1024)

// ---------------- static scratch (allocation-free rule) ----------------
__device__ float  d_XL1[(size_t)NN * HC];
__device__ float  d_XR1[(size_t)NN * HC];
__device__ float  d_H1 [(size_t)NN * HC];
__device__ float  d_XL2[(size_t)NN * C2];
__device__ float  d_XR2[(size_t)NN * C2];
__device__ int    d_deg[NN];
__device__ int    d_cur[NN];
__device__ int    d_row[NN + 1];
__device__ int    d_bsum[NBLK];
__device__ int2   d_eidx[EE];                  // {src, bitcast(ew)}
__device__ float  d_gsum[GG * C2];
__device__ float  d_gcnt[GG];
__device__ int    d_is64;

__device__ __forceinline__ int ld_idx(const void* p, size_t i) {
    return d_is64 ? (int)((const long long*)p)[i] : ((const int*)p)[i];
}

// ---------------- helpers ----------------
__device__ __forceinline__ void load8(float* d, const float* p) {
    float4 a = *(const float4*)p;
    float4 b = *(const float4*)(p + 4);
    d[0]=a.x; d[1]=a.y; d[2]=a.z; d[3]=a.w;
    d[4]=b.x; d[5]=b.y; d[6]=b.z; d[7]=b.w;
}
__device__ __forceinline__ void store8(float* p, const float* d) {
    *(float4*)p       = make_float4(d[0],d[1],d[2],d[3]);
    *(float4*)(p + 4) = make_float4(d[4],d[5],d[6],d[7]);
}

__device__ __forceinline__ unsigned f2tf32(float f) {
    unsigned r;
    asm("cvt.rna.tf32.f32 %0, %1;" : "=r"(r) : "f"(f));
    return r;
}

__device__ __forceinline__ void mma_tf32(float* c, const unsigned* a, const unsigned* b) {
    asm("mma.sync.aligned.m16n8k8.row.col.f32.tf32.tf32.f32 "
        "{%0,%1,%2,%3}, {%4,%5,%6,%7}, {%8,%9}, {%0,%1,%2,%3};"
        : "+f"(c[0]), "+f"(c[1]), "+f"(c[2]), "+f"(c[3])
        : "r"(a[0]), "r"(a[1]), "r"(a[2]), "r"(a[3]), "r"(b[0]), "r"(b[1]));
}

// ---------------- init: zero scratch + index-dtype detect ----------------
__global__ void k_init(const void* ei) {
    int i = blockIdx.x * blockDim.x + threadIdx.x;
    if (i < NN) { d_deg[i] = 0; d_cur[i] = 0; }
    if (i < GG * C2) d_gsum[i] = 0.f;
    if (i < GG) d_gcnt[i] = 0.f;
    if (blockIdx.x == 0 && threadIdx.x < 32) {
        int t = threadIdx.x;
        const long long* p = (const long long*)ei;
        bool ok = true;
        #pragma unroll
        for (int q = 0; q < 2; q++) {
            long long a = p[t + 32 * q];
            long long b = p[(size_t)EE + t + 32 * q];
            ok &= (a >= 0 && a < NN && b >= 0 && b < NN);
        }
        unsigned m = __ballot_sync(0xffffffffu, ok);
        if (t == 0) d_is64 = (m == 0xffffffffu) ? 1 : 0;
    }
}

// ---------------- CSR build ----------------
__global__ void k_hist(const void* __restrict__ ei) {
    int e = blockIdx.x * blockDim.x + threadIdx.x;
    if (e < EE) atomicAdd(&d_deg[ld_idx(ei, (size_t)EE + e)], 1);
}

// phase A: per-block exclusive scan of 1024-element chunk + block total
__global__ void k_scanA() {
    __shared__ int sm[1024];
    int b = blockIdx.x, t = threadIdx.x;
    int i = (b << 10) + t;
    int v = (i < NN) ? d_deg[i] : 0;
    sm[t] = v;
    __syncthreads();
    #pragma unroll 1
    for (int off = 1; off < 1024; off <<= 1) {
        int u = (t >= off) ? sm[t - off] : 0;
        __syncthreads();
        sm[t] += u;
        __syncthreads();
    }
    if (i < NN) d_row[i] = sm[t] - v;               // exclusive prefix
    if (t == 1023) d_bsum[b] = sm[1023];
}

// phase B: add block offsets; block 0 writes the grand total
__global__ void k_scanB() {
    __shared__ int soff;
    int b = blockIdx.x, t = threadIdx.x;
    if (t == 0) {
        int off = 0;
        #pragma unroll 1
        for (int k = 0; k < b; k++) off += d_bsum[k];
        soff = off;
        if (b == 0) {
            int tot = 0;
            #pragma unroll 1
            for (int k = 0; k < NBLK; k++) tot += d_bsum[k];
            d_row[NN] = tot;
        }
    }
    __syncthreads();
    int i = (b << 10) + t;
    if (b > 0 && i < NN) d_row[i] += soff;
}

__global__ void k_scatter(const void* __restrict__ ei,
                          const float* __restrict__ ew) {
    int e = blockIdx.x * blockDim.x + threadIdx.x;
    if (e < EE) {
        int dst = ld_idx(ei, (size_t)EE + e);
        int pos = atomicAdd(&d_cur[dst], 1);
        d_eidx[d_row[dst] + pos] = make_int2(ld_idx(ei, e), __float_as_int(ew[e]));
    }
}

// ---------------- GEMM1 via tf32 tensor cores ---------------------------
__global__ void __launch_bounds__(256, 2)
k_gemm1_tc(const float* __restrict__ X,
           const float* __restrict__ WL, const float* __restrict__ bL,
           const float* __restrict__ WR, const float* __restrict__ bR,
           float* __restrict__ outL, float* __restrict__ outR) {
    const int mat = blockIdx.y >> 1;
    const int nt  = blockIdx.y & 1;
    const float* W    = mat ? WR : WL;
    const float* bias = mat ? bR : bL;
    float* out        = mat ? outR : outL;

    __shared__ float As[128][36];
    __shared__ float Ws[32][132];

    const int t = threadIdx.x;
    const int warp = t >> 5, lane = t & 31;
    const int g = lane >> 2, tig = lane & 3;
    const int m0 = blockIdx.x << 7;
    const int n0 = nt << 7;
    const int wm = (warp >> 2) << 6;
    const int wn = (warp & 3) << 5;

    float acc[4][4][4];
    #pragma unroll
    for (int a = 0; a < 4; a++)
        #pragma unroll
        for (int b = 0; b < 4; b++)
            #pragma unroll
            for (int c = 0; c < 4; c++) acc[a][b][c] = 0.f;

    #pragma unroll 1
    for (int kc = 0; kc < 4; kc++) {
        const int k0 = kc << 5;
        #pragma unroll
        for (int q = t; q < 1024; q += 256) {
            int r  = q >> 3;
            int c4 = (q & 7) << 2;
            int row = m0 + r;
            float4 v = (row < NN) ? *(const float4*)(X + (size_t)row * 128 + k0 + c4)
                                  : make_float4(0.f, 0.f, 0.f, 0.f);
            As[r][c4+0] = v.x; As[r][c4+1] = v.y; As[r][c4+2] = v.z; As[r][c4+3] = v.w;
        }
        #pragma unroll
        for (int q = t; q < 1024; q += 256) {
            int kk = q >> 5;
            int c4 = (q & 31) << 2;
            float4 v = *(const float4*)(W + (size_t)(k0 + kk) * 256 + n0 + c4);
            Ws[kk][c4+0] = v.x; Ws[kk][c4+1] = v.y; Ws[kk][c4+2] = v.z; Ws[kk][c4+3] = v.w;
        }
        __syncthreads();
        #pragma unroll
        for (int ks = 0; ks < 4; ks++) {
            const int kk = ks << 3;
            unsigned a[4][4], b[4][2];
            #pragma unroll
            for (int mi = 0; mi < 4; mi++) {
                int rb = wm + (mi << 4);
                a[mi][0] = f2tf32(As[rb + g    ][kk + tig    ]);
                a[mi][1] = f2tf32(As[rb + g + 8][kk + tig    ]);
                a[mi][2] = f2tf32(As[rb + g    ][kk + tig + 4]);
                a[mi][3] = f2tf32(As[rb + g + 8][kk + tig + 4]);
            }
            #pragma unroll
            for (int ni = 0; ni < 4; ni++) {
                int col = wn + (ni << 3) + g;
                b[ni][0] = f2tf32(Ws[kk + tig    ][col]);
                b[ni][1] = f2tf32(Ws[kk + tig + 4][col]);
            }
            #pragma unroll
            for (int mi = 0; mi < 4; mi++)
                #pragma unroll
                for (int ni = 0; ni < 4; ni++)
                    mma_tf32(acc[mi][ni], a[mi], b[ni]);
        }
        __syncthreads();
    }
    #pragma unroll
    for (int ni = 0; ni < 4; ni++) {
        int col = n0 + wn + (ni << 3) + (tig << 1);
        float b0 = bias[col], b1 = bias[col + 1];
        #pragma unroll
        for (int mi = 0; mi < 4; mi++) {
            int r0 = m0 + wm + (mi << 4) + g;
            if (r0 < NN)
                *(float2*)(out + (size_t)r0 * 256 + col)
                    = make_float2(acc[mi][ni][0] + b0, acc[mi][ni][1] + b1);
            if (r0 + 8 < NN)
                *(float2*)(out + (size_t)(r0 + 8) * 256 + col)
                    = make_float2(acc[mi][ni][2] + b0, acc[mi][ni][3] + b1);
        }
    }
}

// ---------------- GEMM2 via tf32 tensor cores ---------------------------
__global__ void __launch_bounds__(256, 2)
k_gemm2_tc(const float* __restrict__ X,
           const float* __restrict__ WL, const float* __restrict__ bL,
           const float* __restrict__ WR, const float* __restrict__ bR,
           float* __restrict__ outL, float* __restrict__ outR) {
    const float* W    = blockIdx.y ? WR : WL;
    const float* bias = blockIdx.y ? bR : bL;
    float* out        = blockIdx.y ? outR : outL;

    __shared__ float As[128][36];
    __shared__ float Ws[32][36];

    const int t = threadIdx.x;
    const int warp = t >> 5, lane = t & 31;
    const int g = lane >> 2, tig = lane & 3;
    const int m0 = blockIdx.x << 7;
    const int wm = warp << 4;

    float acc[4][4];
    #pragma unroll
    for (int a = 0; a < 4; a++)
        #pragma unroll
        for (int c = 0; c < 4; c++) acc[a][c] = 0.f;

    #pragma unroll 1
    for (int kc = 0; kc < 8; kc++) {
        const int k0 = kc << 5;
        #pragma unroll
        for (int q = t; q < 1024; q += 256) {
            int r  = q >> 3;
            int c4 = (q & 7) << 2;
            int row = m0 + r;
            float4 v = (row < NN) ? *(const float4*)(X + (size_t)row * 256 + k0 + c4)
                                  : make_float4(0.f, 0.f, 0.f, 0.f);
            As[r][c4+0] = v.x; As[r][c4+1] = v.y; As[r][c4+2] = v.z; As[r][c4+3] = v.w;
        }
        if (t < 256) {
            int kk = t >> 3;
            int c4 = (t & 7) << 2;
            float4 v = *(const float4*)(W + (size_t)(k0 + kk) * 32 + c4);
            Ws[kk][c4+0] = v.x; Ws[kk][c4+1] = v.y; Ws[kk][c4+2] = v.z; Ws[kk][c4+3] = v.w;
        }
        __syncthreads();
        #pragma unroll
        for (int ks = 0; ks < 4; ks++) {
            const int kk = ks << 3;
            unsigned a[4], b[4][2];
            a[0] = f2tf32(As[wm + g    ][kk + tig    ]);
            a[1] = f2tf32(As[wm + g + 8][kk + tig    ]);
            a[2] = f2tf32(As[wm + g    ][kk + tig + 4]);
            a[3] = f2tf32(As[wm + g + 8][kk + tig + 4]);
            #pragma unroll
            for (int ni = 0; ni < 4; ni++) {
                int col = (ni << 3) + g;
                b[ni][0] = f2tf32(Ws[kk + tig    ][col]);
                b[ni][1] = f2tf32(Ws[kk + tig + 4][col]);
            }
            #pragma unroll
            for (int ni = 0; ni < 4; ni++)
                mma_tf32(acc[ni], a, b[ni]);
        }
        __syncthreads();
    }
    #pragma unroll
    for (int ni = 0; ni < 4; ni++) {
        int col = (ni << 3) + (tig << 1);
        float b0 = bias[col], b1 = bias[col + 1];
        int r0 = m0 + wm + g;
        if (r0 < NN)
            *(float2*)(out + (size_t)r0 * 32 + col)
                = make_float2(acc[ni][0] + b0, acc[ni][1] + b1);
        if (r0 + 8 < NN)
            *(float2*)(out + (size_t)(r0 + 8) * 32 + col)
                = make_float2(acc[ni][2] + b0, acc[ni][3] + b1);
    }
}

// ---------------- GAT layer 1: warp/node, unroll-2, depth-2 prefetch -----
__device__ __forceinline__ float gat1_edge(const float* xl, const float* xr,
                                           const float* we, const float* at,
                                           float ew) {
    float s = 0.f;
    #pragma unroll
    for (int i = 0; i < 8; i++) {
        float v = xl[i] + xr[i] + ew * we[i];
        v = (v > 0.f) ? v : 0.2f * v;               // leaky_relu 0.2
        s = fmaf(v, at[i], s);
    }
    s += __shfl_xor_sync(0xffffffffu, s, 1);
    s += __shfl_xor_sync(0xffffffffu, s, 2);
    s = fminf(fmaxf(s, -60.f), 60.f);
    return __expf(s);
}

__global__ void k_gat1(const float* __restrict__ We, const float* __restrict__ att,
                       const float* __restrict__ bias) {
    int n    = (blockIdx.x * blockDim.x + threadIdx.x) >> 5;
    int lane = threadIdx.x & 31;
    if (n >= NN) return;
    int base = lane << 3;
    float we[8], at[8], xr[8];
    load8(we, We + base);
    load8(at, att + base);
    load8(xr, d_XR1 + (size_t)n * 256 + base);
    int rs = d_row[n], re = d_row[n + 1];
    int deg = re - rs;
    float denom = 0.f;
    float acc[8];
    #pragma unroll
    for (int i = 0; i < 8; i++) acc[i] = 0.f;
    if (deg > 0) {
        const int2* ep = d_eidx + rs;
        const int last = deg - 1;
        int2 e0 = ep[0];
        int2 e1 = ep[min(1, last)];
        float ew0 = __int_as_float(e0.y), ew1 = __int_as_float(e1.y);
        float xl0[8], xl1[8];
        load8(xl0, d_XL1 + (size_t)e0.x * 256 + base);
        load8(xl1, d_XL1 + (size_t)e1.x * 256 + base);
        #pragma unroll 1
        for (int j = 0; j < deg; j += 2) {
            int2 e2 = ep[min(j + 2, last)];
            int2 e3 = ep[min(j + 3, last)];
            float xl2[8], xl3[8];
            load8(xl2, d_XL1 + (size_t)e2.x * 256 + base);
            load8(xl3, d_XL1 + (size_t)e3.x * 256 + base);
            float p0 = gat1_edge(xl0, xr, we, at, ew0);
            denom += p0;
            #pragma unroll
            for (int i = 0; i < 8; i++) acc[i] = fmaf(p0, xl0[i], acc[i]);
            if (j + 1 < deg) {
                float p1 = gat1_edge(xl1, xr, we, at, ew1);
                denom += p1;
                #pragma unroll
                for (int i = 0; i < 8; i++) acc[i] = fmaf(p1, xl1[i], acc[i]);
            }
            #pragma unroll
            for (int i = 0; i < 8; i++) { xl0[i] = xl2[i]; xl1[i] = xl3[i]; }
            ew0 = __int_as_float(e2.y); ew1 = __int_as_float(e3.y);
        }
    }
    float inv = (deg > 0) ? 1.f / denom : 0.f;
    float bi[8], o[8];
    load8(bi, bias + base);
    #pragma unroll
    for (int i = 0; i < 8; i++) {
        float v = fmaf(acc[i], inv, bi[i]);
        o[i] = (v > 0.f) ? v : (__expf(v) - 1.f);   // elu fused
    }
    store8(d_H1 + (size_t)n * 256 + base, o);
}

// ---------------- GAT layer 2 (H=1,C=32) + pooling, unroll-2 -------------
__device__ __forceinline__ float gat2_edge(float xl, float xr, float we,
                                           float at, float ew) {
    float v = xl + xr + ew * we;
    v = (v > 0.f) ? v : 0.2f * v;
    float s = v * at;
    #pragma unroll
    for (int o = 16; o > 0; o >>= 1) s += __shfl_xor_sync(0xffffffffu, s, o);
    s = fminf(fmaxf(s, -60.f), 60.f);
    return __expf(s);
}

__global__ void k_gat2(const float* __restrict__ We, const float* __restrict__ att,
                       const float* __restrict__ bias,
                       const void* __restrict__ batch) {
    int n    = (blockIdx.x * blockDim.x + threadIdx.x) >> 5;
    int lane = threadIdx.x & 31;
    if (n >= NN) return;
    float we = We[lane], at = att[lane];
    float xr = d_XR2[(size_t)n * 32 + lane];
    int rs = d_row[n], re = d_row[n + 1];
    int deg = re - rs;
    float denom = 0.f, acc = 0.f;
    if (deg > 0) {
        const int2* ep = d_eidx + rs;
        const int last = deg - 1;
        int2 e0 = ep[0];
        int2 e1 = ep[min(1, last)];
        float ew0 = __int_as_float(e0.y), ew1 = __int_as_float(e1.y);
        float xl0 = d_XL2[(size_t)e0.x * 32 + lane];
        float xl1 = d_XL2[(size_t)e1.x * 32 + lane];
        #pragma unroll 1
        for (int j = 0; j < deg; j += 2) {
            int2 e2 = ep[min(j + 2, last)];
            int2 e3 = ep[min(j + 3, last)];
            float xl2 = d_XL2[(size_t)e2.x * 32 + lane];
            float xl3 = d_XL2[(size_t)e3.x * 32 + lane];
            float p0 = gat2_edge(xl0, xr, we, at, ew0);
            denom += p0;
            acc = fmaf(p0, xl0, acc);
            if (j + 1 < deg) {
                float p1 = gat2_edge(xl1, xr, we, at, ew1);
                denom += p1;
                acc = fmaf(p1, xl1, acc);
            }
            xl0 = xl2; xl1 = xl3;
            ew0 = __int_as_float(e2.y); ew1 = __int_as_float(e3.y);
        }
    }
    float val = ((deg > 0) ? acc / denom : 0.f) + bias[lane];
    int g = ld_idx(batch, n);
    atomicAdd(&d_gsum[g * 32 + lane], val);
    if (lane == 0) atomicAdd(&d_gcnt[g], 1.f);
}

// ---------------- head ----------------
__global__ void k_head(const float* __restrict__ Wlin, const float* __restrict__ blin,
                       float* __restrict__ out) {
    __shared__ float logits[GG * 10];
    __shared__ float mrow[GG], lse[GG];
    int t = threadIdx.x;                            // 640 threads
    if (t < GG * 10) {
        int g = t / 10, o = t % 10;
        float cnt = fmaxf(d_gcnt[g], 1.f);
        float inv = 1.f / cnt;
        float acc = blin[o];
        #pragma unroll
        for (int c = 0; c < 32; c++)
            acc = fmaf(d_gsum[g * 32 + c] * inv, Wlin[c * 10 + o], acc);
        logits[t] = acc;
    }
    __syncthreads();
    if (t < GG) {
        float mx = -1e30f;
        #pragma unroll
        for (int o = 0; o < 10; o++) mx = fmaxf(mx, logits[t * 10 + o]);
        float s = 0.f;
        #pragma unroll
        for (int o = 0; o < 10; o++) s += expf(logits[t * 10 + o] - mx);
        mrow[t] = mx; lse[t] = logf(s);
    }
    __syncthreads();
    if (t < GG * 10) {
        int g = t / 10;
        out[t] = logits[t] - mrow[g] - lse[g];
    }
}

// ---------------- launch ----------------
extern "C" void kernel_launch(void* const* d_in, const int* in_sizes, int n_in,
                              void* d_out, int out_size) {
    const float* x     = (const float*)d_in[0];
    const float* ew    = (const float*)d_in[1];
    const float* Wl1   = (const float*)d_in[2];
    const float* bl1   = (const float*)d_in[3];
    const float* Wr1   = (const float*)d_in[4];
    const float* br1   = (const float*)d_in[5];
    const float* We1   = (const float*)d_in[6];
    const float* att1  = (const float*)d_in[7];
    const float* bias1 = (const float*)d_in[8];
    const float* Wl2   = (const float*)d_in[9];
    const float* bl2   = (const float*)d_in[10];
    const float* Wr2   = (const float*)d_in[11];
    const float* br2   = (const float*)d_in[12];
    const float* We2   = (const float*)d_in[13];
    const float* att2  = (const float*)d_in[14];
    const float* bias2 = (const float*)d_in[15];
    const float* Wlin  = (const float*)d_in[16];
    const float* blin  = (const float*)d_in[17];
    const void*  ei    = d_in[18];
    const void*  batch = d_in[19];
    float* out = (float*)d_out;

    void *pXL1, *pXR1, *pH1, *pXL2, *pXR2;
    cudaGetSymbolAddress(&pXL1, d_XL1);
    cudaGetSymbolAddress(&pXR1, d_XR1);
    cudaGetSymbolAddress(&pH1,  d_H1);
    cudaGetSymbolAddress(&pXL2, d_XL2);
    cudaGetSymbolAddress(&pXR2, d_XR2);

    // one-time host objects for the capture fork (no device memory involved)
    static cudaStream_t s2 = nullptr;
    static cudaEvent_t  evFork = nullptr, evJoin = nullptr;
    if (s2 == nullptr) {
        cudaStreamCreateWithFlags(&s2, cudaStreamNonBlocking);
        cudaEventCreateWithFlags(&evFork, cudaEventDisableTiming);
        cudaEventCreateWithFlags(&evJoin, cudaEventDisableTiming);
    }

    // fork: gemm1 (needs only x/W) runs concurrently with the CSR build
    cudaEventRecord(evFork, 0);
    cudaStreamWaitEvent(s2, evFork, 0);
    k_gemm1_tc<<<dim3((NN + 127) / 128, 4), 256, 0, s2>>>(
        x, Wl1, bl1, Wr1, br1, (float*)pXL1, (float*)pXR1);
    cudaEventRecord(evJoin, s2);

    // CSR chain on the main (captured) stream
    k_init<<<(NN + 255) / 256, 256>>>(ei);
    k_hist<<<(EE + 255) / 256, 256>>>(ei);
    k_scanA<<<NBLK, 1024>>>();
    k_scanB<<<NBLK, 1024>>>();
    k_scatter<<<(EE + 255) / 256, 256>>>(ei, ew);

    // join: gat1 needs both gemm1 outputs and the CSR
    cudaStreamWaitEvent(0, evJoin, 0);
    k_gat1<<<(NN * 32) / 256, 256>>>(We1, att1, bias1);
    k_gemm2_tc<<<dim3((NN + 127) / 128, 2), 256>>>((const float*)pH1, Wl2, bl2, Wr2, br2,
                                                   (float*)pXL2, (float*)pXR2);
    k_gat2<<<(NN * 32) / 256, 256>>>(We2, att2, bias2, batch);
    k_head<<<1, 640>>>(Wlin, blin, out);
}